// round 2
// baseline (speedup 1.0000x reference)
#include <cuda_runtime.h>
#include <cstdint>

#define T_TOK 16384
#define DIM   1024
#define HID   4096

#define BM 128
#define BN 128
#define BK 16
#define PAD 17   // smem row stride (u32 units) to break bank conflicts

// ---------------- scratch (static __device__ — allocation-free) ----------------
__device__ float g_H[(size_t)T_TOK * HID];   // gathered-order hidden activations
__device__ int   g_perm[T_TOK];              // gathered row -> token id
__device__ int   g_rowd[T_TOK];              // gathered row -> d (=128<<expert)
__device__ int   g_cnt[4];
__device__ int   g_off[4];
__device__ int   g_cur[4];

// ---------------- token sort (counting sort by expert) ----------------
__global__ void k_zero() {
    if (threadIdx.x < 4) { g_cnt[threadIdx.x] = 0; g_cur[threadIdx.x] = 0; }
}

__global__ void k_count(const int* __restrict__ mask) {
    int t = blockIdx.x * blockDim.x + threadIdx.x;
    if (t < T_TOK) atomicAdd(&g_cnt[mask[t]], 1);
}

__global__ void k_offsets() {
    int s = 0;
    for (int e = 0; e < 4; e++) { g_off[e] = s; s += g_cnt[e]; }
}

__global__ void k_scatter(const int* __restrict__ mask) {
    int t = blockIdx.x * blockDim.x + threadIdx.x;
    if (t < T_TOK) {
        int e = mask[t];
        int p = g_off[e] + atomicAdd(&g_cur[e], 1);
        g_perm[p] = t;
        g_rowd[p] = 128 << e;
    }
}

// ---------------- helpers ----------------
__device__ __forceinline__ uint32_t f2tf(float x) {
    uint32_t r;
    asm("cvt.rna.tf32.f32 %0, %1;" : "=r"(r) : "f"(x));
    return r;
}

__device__ __forceinline__ void mma8(float* c,
                                     uint32_t a0, uint32_t a1, uint32_t a2, uint32_t a3,
                                     uint32_t b0, uint32_t b1) {
    asm volatile(
        "mma.sync.aligned.m16n8k8.row.col.f32.tf32.tf32.f32 "
        "{%0,%1,%2,%3}, {%4,%5,%6,%7}, {%8,%9}, {%0,%1,%2,%3};\n"
        : "+f"(c[0]), "+f"(c[1]), "+f"(c[2]), "+f"(c[3])
        : "r"(a0), "r"(a1), "r"(a2), "r"(a3), "r"(b0), "r"(b1));
}

__device__ __forceinline__ float gelu_exact(float v) {
    return 0.5f * v * (1.0f + erff(v * 0.70710678118654752f));
}

// ---------------- GEMM1: H = gelu(Xmask @ W1^T + b1), gathered rows ----------------
__global__ __launch_bounds__(256, 2)
void k_gemm1(const float* __restrict__ x, const float* __restrict__ w1,
             const float* __restrict__ b1) {
    __shared__ uint32_t As[BM * PAD];
    __shared__ uint32_t Bs[BN * PAD];

    const int n0   = blockIdx.x * BN;   // hidden-feature tile
    const int row0 = blockIdx.y * BM;   // gathered token tile

    const int tid  = threadIdx.x;
    const int lane = tid & 31;
    const int wid  = tid >> 5;
    const int wm   = wid >> 2;          // 0..1 : warp row (64 rows)
    const int wn   = wid & 3;           // 0..3 : warp col (32 cols)

    // load assignment: 2 threads per row, 8 floats each
    const int lr = tid >> 1;
    const int lh = tid & 1;

    const int tok = g_perm[row0 + lr];
    const int dA  = g_rowd[row0 + lr];
    const float* aptr = x  + (size_t)tok * DIM + lh * 8;
    const float* bptr = w1 + (size_t)(n0 + lr) * DIM + lh * 8;

    // rows sorted by expert => max d in tile is the last row's d
    const int kmax = g_rowd[row0 + BM - 1];

    float acc[4][4][4];
#pragma unroll
    for (int mi = 0; mi < 4; mi++)
#pragma unroll
        for (int ni = 0; ni < 4; ni++)
#pragma unroll
            for (int r = 0; r < 4; r++) acc[mi][ni][r] = 0.0f;

    for (int k0 = 0; k0 < kmax; k0 += BK) {
        float4 a0v = make_float4(0.f, 0.f, 0.f, 0.f);
        float4 a1v = make_float4(0.f, 0.f, 0.f, 0.f);
        if (k0 < dA) {   // d is a multiple of 128 >= 128, k0 multiple of 16 => whole chunk in/out
            a0v = *(const float4*)(aptr + k0);
            a1v = *(const float4*)(aptr + k0 + 4);
        }
        const float4 b0v = *(const float4*)(bptr + k0);
        const float4 b1v = *(const float4*)(bptr + k0 + 4);

        __syncthreads();
        uint32_t* as = &As[lr * PAD + lh * 8];
        as[0] = f2tf(a0v.x); as[1] = f2tf(a0v.y); as[2] = f2tf(a0v.z); as[3] = f2tf(a0v.w);
        as[4] = f2tf(a1v.x); as[5] = f2tf(a1v.y); as[6] = f2tf(a1v.z); as[7] = f2tf(a1v.w);
        uint32_t* bs = &Bs[lr * PAD + lh * 8];
        bs[0] = f2tf(b0v.x); bs[1] = f2tf(b0v.y); bs[2] = f2tf(b0v.z); bs[3] = f2tf(b0v.w);
        bs[4] = f2tf(b1v.x); bs[5] = f2tf(b1v.y); bs[6] = f2tf(b1v.z); bs[7] = f2tf(b1v.w);
        __syncthreads();

#pragma unroll
        for (int ks = 0; ks < 2; ks++) {
            uint32_t af[4][4];
            uint32_t bf[4][2];
            const int kk = ks * 8 + (lane & 3);
#pragma unroll
            for (int mi = 0; mi < 4; mi++) {
                const int m = wm * 64 + mi * 16 + (lane >> 2);
                af[mi][0] = As[m * PAD + kk];
                af[mi][1] = As[(m + 8) * PAD + kk];
                af[mi][2] = As[m * PAD + kk + 4];
                af[mi][3] = As[(m + 8) * PAD + kk + 4];
            }
#pragma unroll
            for (int ni = 0; ni < 4; ni++) {
                const int n = wn * 32 + ni * 8 + (lane >> 2);
                bf[ni][0] = Bs[n * PAD + kk];
                bf[ni][1] = Bs[n * PAD + kk + 4];
            }
#pragma unroll
            for (int mi = 0; mi < 4; mi++)
#pragma unroll
                for (int ni = 0; ni < 4; ni++)
                    mma8(acc[mi][ni], af[mi][0], af[mi][1], af[mi][2], af[mi][3],
                         bf[ni][0], bf[ni][1]);
        }
    }

    // epilogue: bias + exact gelu -> g_H (gathered order)
#pragma unroll
    for (int mi = 0; mi < 4; mi++) {
        const int mrowA = wm * 64 + mi * 16 + (lane >> 2);
#pragma unroll
        for (int half = 0; half < 2; half++) {
            const int mrow = mrowA + half * 8;
            float* hp = g_H + (size_t)(row0 + mrow) * HID;
#pragma unroll
            for (int ni = 0; ni < 4; ni++) {
                const int col = n0 + wn * 32 + ni * 8 + 2 * (lane & 3);
                const float2 bb = *(const float2*)(b1 + col);
                float v0 = gelu_exact(acc[mi][ni][half * 2 + 0] + bb.x);
                float v1 = gelu_exact(acc[mi][ni][half * 2 + 1] + bb.y);
                *(float2*)(hp + col) = make_float2(v0, v1);
            }
        }
    }
}

// ---------------- GEMM2: Y = mask_out(H @ W2^T + b2), scattered to tokens ----------------
__global__ __launch_bounds__(256, 2)
void k_gemm2(const float* __restrict__ w2, const float* __restrict__ b2,
             float* __restrict__ out) {
    __shared__ uint32_t As[BM * PAD];
    __shared__ uint32_t Bs[BN * PAD];

    const int n0   = blockIdx.x * BN;
    const int row0 = blockIdx.y * BM;
    const int dmax = g_rowd[row0 + BM - 1];

    const int tid  = threadIdx.x;
    const int lane = tid & 31;
    const int wid  = tid >> 5;
    const int wm   = wid >> 2;
    const int wn   = wid & 3;
    const int lr   = tid >> 1;
    const int lh   = tid & 1;

    if (n0 >= dmax) {
        // entire output tile is masked to zero; just write zeros
        const int tok = g_perm[row0 + lr];
        float4* op = (float4*)(out + (size_t)tok * DIM + n0 + lh * 64);
        const float4 z = make_float4(0.f, 0.f, 0.f, 0.f);
#pragma unroll
        for (int j = 0; j < 16; j++) op[j] = z;
        return;
    }

    const float* aptr = g_H + (size_t)(row0 + lr) * HID + lh * 8;
    const float* bptr = w2  + (size_t)(n0 + lr) * HID + lh * 8;

    float acc[4][4][4];
#pragma unroll
    for (int mi = 0; mi < 4; mi++)
#pragma unroll
        for (int ni = 0; ni < 4; ni++)
#pragma unroll
            for (int r = 0; r < 4; r++) acc[mi][ni][r] = 0.0f;

    for (int k0 = 0; k0 < HID; k0 += BK) {
        const float4 a0v = *(const float4*)(aptr + k0);
        const float4 a1v = *(const float4*)(aptr + k0 + 4);
        const float4 b0v = *(const float4*)(bptr + k0);
        const float4 b1v = *(const float4*)(bptr + k0 + 4);

        __syncthreads();
        uint32_t* as = &As[lr * PAD + lh * 8];
        as[0] = f2tf(a0v.x); as[1] = f2tf(a0v.y); as[2] = f2tf(a0v.z); as[3] = f2tf(a0v.w);
        as[4] = f2tf(a1v.x); as[5] = f2tf(a1v.y); as[6] = f2tf(a1v.z); as[7] = f2tf(a1v.w);
        uint32_t* bs = &Bs[lr * PAD + lh * 8];
        bs[0] = f2tf(b0v.x); bs[1] = f2tf(b0v.y); bs[2] = f2tf(b0v.z); bs[3] = f2tf(b0v.w);
        bs[4] = f2tf(b1v.x); bs[5] = f2tf(b1v.y); bs[6] = f2tf(b1v.z); bs[7] = f2tf(b1v.w);
        __syncthreads();

#pragma unroll
        for (int ks = 0; ks < 2; ks++) {
            uint32_t af[4][4];
            uint32_t bf[4][2];
            const int kk = ks * 8 + (lane & 3);
#pragma unroll
            for (int mi = 0; mi < 4; mi++) {
                const int m = wm * 64 + mi * 16 + (lane >> 2);
                af[mi][0] = As[m * PAD + kk];
                af[mi][1] = As[(m + 8) * PAD + kk];
                af[mi][2] = As[m * PAD + kk + 4];
                af[mi][3] = As[(m + 8) * PAD + kk + 4];
            }
#pragma unroll
            for (int ni = 0; ni < 4; ni++) {
                const int n = wn * 32 + ni * 8 + (lane >> 2);
                bf[ni][0] = Bs[n * PAD + kk];
                bf[ni][1] = Bs[n * PAD + kk + 4];
            }
#pragma unroll
            for (int mi = 0; mi < 4; mi++)
#pragma unroll
                for (int ni = 0; ni < 4; ni++)
                    mma8(acc[mi][ni], af[mi][0], af[mi][1], af[mi][2], af[mi][3],
                         bf[ni][0], bf[ni][1]);
        }
    }

    // epilogue: bias + output mask, scatter back to token order
#pragma unroll
    for (int mi = 0; mi < 4; mi++) {
        const int mrowA = wm * 64 + mi * 16 + (lane >> 2);
#pragma unroll
        for (int half = 0; half < 2; half++) {
            const int mrow = mrowA + half * 8;
            const int gr   = row0 + mrow;
            const int tok  = g_perm[gr];
            const int d    = g_rowd[gr];
            float* op = out + (size_t)tok * DIM;
#pragma unroll
            for (int ni = 0; ni < 4; ni++) {
                const int col = n0 + wn * 32 + ni * 8 + 2 * (lane & 3);
                float2 r;
                if (col < d) {   // d multiple of 128, col even => pair is uniform
                    const float2 bb = *(const float2*)(b2 + col);
                    r = make_float2(acc[mi][ni][half * 2 + 0] + bb.x,
                                    acc[mi][ni][half * 2 + 1] + bb.y);
                } else {
                    r = make_float2(0.f, 0.f);
                }
                *(float2*)(op + col) = r;
            }
        }
    }
}

// ---------------- launch ----------------
extern "C" void kernel_launch(void* const* d_in, const int* in_sizes, int n_in,
                              void* d_out, int out_size) {
    const float* x    = (const float*)d_in[0];
    const float* w1   = (const float*)d_in[1];
    const float* b1   = (const float*)d_in[2];
    const float* w2   = (const float*)d_in[3];
    const float* b2   = (const float*)d_in[4];
    const int*   mask = (const int*)d_in[5];
    float* out = (float*)d_out;

    k_zero<<<1, 32>>>();
    k_count<<<T_TOK / 256, 256>>>(mask);
    k_offsets<<<1, 1>>>();
    k_scatter<<<T_TOK / 256, 256>>>(mask);

    dim3 g1(HID / BN, T_TOK / BM);
    k_gemm1<<<g1, 256>>>(x, w1, b1);

    dim3 g2(DIM / BN, T_TOK / BM);
    k_gemm2<<<g2, 256>>>(w2, b2, out);
}

// round 3
// speedup vs baseline: 2.2741x; 2.2741x over previous
#include <cuda_runtime.h>
#include <cstdint>

#define T_TOK 16384
#define DIM   1024
#define HID   4096

#define BM 128
#define BN 256
#define BK 16
#define PAD 20                        // u32 row stride: conflict-free for mma frag pattern
#define A_STRIDE (BM * PAD)           // 2560 u32
#define B_STRIDE (BN * PAD)           // 5120 u32
#define STAGE_U32 (A_STRIDE + B_STRIDE)
#define SMEM_BYTES (2 * STAGE_U32 * 4)   // 61440 B, dynamic

// ---------------- scratch (static __device__ — allocation-free) ----------------
__device__ uint32_t g_H[(size_t)T_TOK * HID];     // hidden acts, gathered order, tf32 bits
__device__ uint32_t g_w1t[(size_t)HID * DIM];     // w1 pre-converted to tf32
__device__ uint32_t g_w2t[(size_t)DIM * HID];     // w2 pre-converted to tf32
__device__ int g_perm[T_TOK];
__device__ int g_rowd[T_TOK];
__device__ int g_cnt[4], g_off[4], g_cur[4];

// ---------------- token sort ----------------
__global__ void k_zero() {
    if (threadIdx.x < 4) { g_cnt[threadIdx.x] = 0; g_cur[threadIdx.x] = 0; }
}
__global__ void k_count(const int* __restrict__ mask) {
    int t = blockIdx.x * blockDim.x + threadIdx.x;
    if (t < T_TOK) atomicAdd(&g_cnt[mask[t]], 1);
}
__global__ void k_offsets() {
    int s = 0;
    for (int e = 0; e < 4; e++) { g_off[e] = s; s += g_cnt[e]; }
}
__global__ void k_scatter(const int* __restrict__ mask) {
    int t = blockIdx.x * blockDim.x + threadIdx.x;
    if (t < T_TOK) {
        int e = mask[t];
        int p = g_off[e] + atomicAdd(&g_cur[e], 1);
        g_perm[p] = t;
        g_rowd[p] = 128 << e;
    }
}

// ---------------- helpers ----------------
__device__ __forceinline__ uint32_t f2tf(float x) {
    uint32_t r;
    asm("cvt.rna.tf32.f32 %0, %1;" : "=r"(r) : "f"(x));
    return r;
}
__device__ __forceinline__ void mma8(float* c,
                                     uint32_t a0, uint32_t a1, uint32_t a2, uint32_t a3,
                                     uint32_t b0, uint32_t b1) {
    asm volatile(
        "mma.sync.aligned.m16n8k8.row.col.f32.tf32.tf32.f32 "
        "{%0,%1,%2,%3}, {%4,%5,%6,%7}, {%8,%9}, {%0,%1,%2,%3};\n"
        : "+f"(c[0]), "+f"(c[1]), "+f"(c[2]), "+f"(c[3])
        : "r"(a0), "r"(a1), "r"(a2), "r"(a3), "r"(b0), "r"(b1));
}
__device__ __forceinline__ float gelu_exact(float v) {
    return 0.5f * v * (1.0f + erff(v * 0.70710678118654752f));
}
__device__ __forceinline__ void cpa16(uint32_t saddr, const void* g) {
    asm volatile("cp.async.cg.shared.global [%0], [%1], 16;\n" :: "r"(saddr), "l"(g));
}
__device__ __forceinline__ void cp_commit() {
    asm volatile("cp.async.commit_group;\n" ::: "memory");
}
__device__ __forceinline__ void cp_wait0() {
    asm volatile("cp.async.wait_group 0;\n" ::: "memory");
}

// ---------------- weight pre-conversion f32 -> tf32 bits ----------------
__global__ void k_cvt(const float* __restrict__ w1, const float* __restrict__ w2) {
    const int i = blockIdx.x * blockDim.x + threadIdx.x;
    const int n1 = HID * DIM / 4;
    if (i < n1) {
        float4 v = ((const float4*)w1)[i];
        uint4 r = make_uint4(f2tf(v.x), f2tf(v.y), f2tf(v.z), f2tf(v.w));
        ((uint4*)g_w1t)[i] = r;
    } else {
        const int j = i - n1;
        float4 v = ((const float4*)w2)[j];
        uint4 r = make_uint4(f2tf(v.x), f2tf(v.y), f2tf(v.z), f2tf(v.w));
        ((uint4*)g_w2t)[j] = r;
    }
}

// ---------------- shared compute: one BK=16 tile, warp tile 64x64 ----------------
__device__ __forceinline__ void tile_compute(const uint32_t* __restrict__ As,
                                             const uint32_t* __restrict__ Bs,
                                             float (&acc)[4][8][4],
                                             int wm, int wn, int lane) {
#pragma unroll
    for (int ks = 0; ks < 2; ks++) {
        const int kk = ks * 8 + (lane & 3);
        uint32_t af[4][4];
        uint32_t bf[8][2];
        const int mrow = wm * 64 + (lane >> 2);
#pragma unroll
        for (int mi = 0; mi < 4; mi++) {
            const uint32_t* p = As + (mrow + mi * 16) * PAD + kk;
            af[mi][0] = p[0];
            af[mi][1] = p[8 * PAD];
            af[mi][2] = p[4];
            af[mi][3] = p[8 * PAD + 4];
        }
        const int ncol = wn * 64 + (lane >> 2);
#pragma unroll
        for (int ni = 0; ni < 8; ni++) {
            const uint32_t* p = Bs + (ncol + ni * 8) * PAD + kk;
            bf[ni][0] = p[0];
            bf[ni][1] = p[4];
        }
#pragma unroll
        for (int mi = 0; mi < 4; mi++)
#pragma unroll
            for (int ni = 0; ni < 8; ni++)
                mma8(acc[mi][ni], af[mi][0], af[mi][1], af[mi][2], af[mi][3],
                     bf[ni][0], bf[ni][1]);
    }
}

// issue the 4 B-row cp.asyncs for this thread into stage base sdst (byte smem addr)
__device__ __forceinline__ void issue_b4(uint32_t sdst,
                                         const uint32_t* b0, const uint32_t* b1,
                                         const uint32_t* b2, const uint32_t* b3, int k0) {
    cpa16(sdst, b0 + k0);
    cpa16(sdst + 64 * PAD * 4, b1 + k0);
    cpa16(sdst + 128 * PAD * 4, b2 + k0);
    cpa16(sdst + 192 * PAD * 4, b3 + k0);
}

// ---------------- GEMM1: H = gelu(Xmask @ W1^T + b1) (tf32 bits out) ----------------
__global__ void __launch_bounds__(256, 1)
k_gemm1(const float* __restrict__ x, const float* __restrict__ b1) {
    extern __shared__ uint32_t sm[];
    const uint32_t sbase = (uint32_t)__cvta_generic_to_shared(sm);

    const int n0   = blockIdx.x * BN;
    const int row0 = blockIdx.y * BM;
    const int tid  = threadIdx.x;
    const int lane = tid & 31, wid = tid >> 5;
    const int wm = wid >> 2, wn = wid & 3;
    const int ar = tid >> 2, q = tid & 3;

    const int dA0 = g_rowd[row0 + ar];
    const int dA1 = g_rowd[row0 + ar + 64];
    const float* ap0 = x + (size_t)g_perm[row0 + ar] * DIM + q * 4;
    const float* ap1 = x + (size_t)g_perm[row0 + ar + 64] * DIM + q * 4;

    const uint32_t* bp0 = g_w1t + (size_t)(n0 + ar) * DIM + q * 4;
    const uint32_t* bp1 = g_w1t + (size_t)(n0 + ar + 64) * DIM + q * 4;
    const uint32_t* bp2 = g_w1t + (size_t)(n0 + ar + 128) * DIM + q * 4;
    const uint32_t* bp3 = g_w1t + (size_t)(n0 + ar + 192) * DIM + q * 4;

    const uint32_t boff0 = sbase + (A_STRIDE + ar * PAD + q * 4) * 4;

    const int kmax = g_rowd[row0 + BM - 1];   // sorted rows -> last is max
    const int nk = kmax / BK;

    float acc[4][8][4];
#pragma unroll
    for (int mi = 0; mi < 4; mi++)
#pragma unroll
        for (int ni = 0; ni < 8; ni++)
#pragma unroll
            for (int r = 0; r < 4; r++) acc[mi][ni][r] = 0.0f;

    const float4 fz = make_float4(0.f, 0.f, 0.f, 0.f);
    float4 ra0, ra1;

    // prologue: stage 0
    issue_b4(boff0, bp0, bp1, bp2, bp3, 0);
    cp_commit();
    ra0 = *(const float4*)ap0;   // k=0 always < d
    ra1 = *(const float4*)ap1;
    {
        uint32_t* p0 = sm + ar * PAD + q * 4;
        p0[0] = f2tf(ra0.x); p0[1] = f2tf(ra0.y); p0[2] = f2tf(ra0.z); p0[3] = f2tf(ra0.w);
        uint32_t* p1 = sm + (ar + 64) * PAD + q * 4;
        p1[0] = f2tf(ra1.x); p1[1] = f2tf(ra1.y); p1[2] = f2tf(ra1.z); p1[3] = f2tf(ra1.w);
    }
    cp_wait0();
    __syncthreads();

    for (int it = 0; it < nk; it++) {
        const int cur = it & 1;
        const int nxt = cur ^ 1;
        const bool hn = (it + 1) < nk;
        if (hn) {
            const int k0 = (it + 1) * BK;
            issue_b4(boff0 + nxt * STAGE_U32 * 4, bp0, bp1, bp2, bp3, k0);
            cp_commit();
            ra0 = (k0 < dA0) ? *(const float4*)(ap0 + k0) : fz;
            ra1 = (k0 < dA1) ? *(const float4*)(ap1 + k0) : fz;
        }
        tile_compute(sm + cur * STAGE_U32, sm + cur * STAGE_U32 + A_STRIDE,
                     acc, wm, wn, lane);
        if (hn) {
            uint32_t* s = sm + nxt * STAGE_U32;
            uint32_t* p0 = s + ar * PAD + q * 4;
            p0[0] = f2tf(ra0.x); p0[1] = f2tf(ra0.y); p0[2] = f2tf(ra0.z); p0[3] = f2tf(ra0.w);
            uint32_t* p1 = s + (ar + 64) * PAD + q * 4;
            p1[0] = f2tf(ra1.x); p1[1] = f2tf(ra1.y); p1[2] = f2tf(ra1.z); p1[3] = f2tf(ra1.w);
        }
        cp_wait0();
        __syncthreads();
    }

    // epilogue: bias + exact gelu -> tf32 bits into g_H (gathered order)
#pragma unroll
    for (int mi = 0; mi < 4; mi++) {
        const int mrowA = wm * 64 + mi * 16 + (lane >> 2);
#pragma unroll
        for (int half = 0; half < 2; half++) {
            const int grow = row0 + mrowA + half * 8;
            uint32_t* hp = g_H + (size_t)grow * HID;
#pragma unroll
            for (int ni = 0; ni < 8; ni++) {
                const int col = n0 + wn * 64 + ni * 8 + 2 * (lane & 3);
                const float2 bb = *(const float2*)(b1 + col);
                float v0 = gelu_exact(acc[mi][ni][half * 2 + 0] + bb.x);
                float v1 = gelu_exact(acc[mi][ni][half * 2 + 1] + bb.y);
                *(uint2*)(hp + col) = make_uint2(f2tf(v0), f2tf(v1));
            }
        }
    }
}

// ---------------- GEMM2: Y = mask_out(H @ W2^T + b2), scattered ----------------
__global__ void __launch_bounds__(256, 1)
k_gemm2(const float* __restrict__ b2, float* __restrict__ out) {
    extern __shared__ uint32_t sm[];
    const uint32_t sbase = (uint32_t)__cvta_generic_to_shared(sm);

    const int n0   = blockIdx.x * BN;
    const int row0 = blockIdx.y * BM;
    const int tid  = threadIdx.x;
    const int dmax = g_rowd[row0 + BM - 1];

    if (n0 >= dmax) {   // whole 256-col tile masked to zero (block-uniform branch)
        const int lr = tid >> 1, lh = tid & 1;
        const int tok = g_perm[row0 + lr];
        float4* op = (float4*)(out + (size_t)tok * DIM + n0 + lh * 128);
        const float4 z = make_float4(0.f, 0.f, 0.f, 0.f);
#pragma unroll
        for (int j = 0; j < 32; j++) op[j] = z;
        return;
    }

    const int lane = tid & 31, wid = tid >> 5;
    const int wm = wid >> 2, wn = wid & 3;
    const int ar = tid >> 2, q = tid & 3;

    const uint32_t* hp0 = g_H + (size_t)(row0 + ar) * HID + q * 4;
    const uint32_t* hp1 = g_H + (size_t)(row0 + ar + 64) * HID + q * 4;
    const uint32_t* bp0 = g_w2t + (size_t)(n0 + ar) * HID + q * 4;
    const uint32_t* bp1 = g_w2t + (size_t)(n0 + ar + 64) * HID + q * 4;
    const uint32_t* bp2 = g_w2t + (size_t)(n0 + ar + 128) * HID + q * 4;
    const uint32_t* bp3 = g_w2t + (size_t)(n0 + ar + 192) * HID + q * 4;

    const uint32_t aoff0 = sbase + (ar * PAD + q * 4) * 4;
    const uint32_t aoff1 = sbase + ((ar + 64) * PAD + q * 4) * 4;
    const uint32_t boff0 = sbase + (A_STRIDE + ar * PAD + q * 4) * 4;

    float acc[4][8][4];
#pragma unroll
    for (int mi = 0; mi < 4; mi++)
#pragma unroll
        for (int ni = 0; ni < 8; ni++)
#pragma unroll
            for (int r = 0; r < 4; r++) acc[mi][ni][r] = 0.0f;

    const int nk = HID / BK;   // 256

    // prologue
    cpa16(aoff0, hp0);
    cpa16(aoff1, hp1);
    issue_b4(boff0, bp0, bp1, bp2, bp3, 0);
    cp_commit();
    cp_wait0();
    __syncthreads();

    for (int it = 0; it < nk; it++) {
        const int cur = it & 1;
        const int nxt = cur ^ 1;
        const bool hn = (it + 1) < nk;
        if (hn) {
            const int k0 = (it + 1) * BK;
            const uint32_t so = nxt * STAGE_U32 * 4;
            cpa16(aoff0 + so, hp0 + k0);
            cpa16(aoff1 + so, hp1 + k0);
            issue_b4(boff0 + so, bp0, bp1, bp2, bp3, k0);
            cp_commit();
        }
        tile_compute(sm + cur * STAGE_U32, sm + cur * STAGE_U32 + A_STRIDE,
                     acc, wm, wn, lane);
        cp_wait0();
        __syncthreads();
    }

    // epilogue: bias + output mask, scatter back to token order
#pragma unroll
    for (int mi = 0; mi < 4; mi++) {
        const int mrowA = wm * 64 + mi * 16 + (lane >> 2);
#pragma unroll
        for (int half = 0; half < 2; half++) {
            const int grow = row0 + mrowA + half * 8;
            const int tok  = g_perm[grow];
            const int d    = g_rowd[grow];
            float* op = out + (size_t)tok * DIM;
#pragma unroll
            for (int ni = 0; ni < 8; ni++) {
                const int col = n0 + wn * 64 + ni * 8 + 2 * (lane & 3);
                float2 r;
                if (col < d) {   // d multiple of 128, col even -> pair uniform
                    const float2 bb = *(const float2*)(b2 + col);
                    r = make_float2(acc[mi][ni][half * 2 + 0] + bb.x,
                                    acc[mi][ni][half * 2 + 1] + bb.y);
                } else {
                    r = make_float2(0.f, 0.f);
                }
                *(float2*)(op + col) = r;
            }
        }
    }
}

// ---------------- launch ----------------
extern "C" void kernel_launch(void* const* d_in, const int* in_sizes, int n_in,
                              void* d_out, int out_size) {
    const float* x    = (const float*)d_in[0];
    const float* w1   = (const float*)d_in[1];
    const float* b1   = (const float*)d_in[2];
    const float* w2   = (const float*)d_in[3];
    const float* b2   = (const float*)d_in[4];
    const int*   mask = (const int*)d_in[5];
    float* out = (float*)d_out;

    cudaFuncSetAttribute(k_gemm1, cudaFuncAttributeMaxDynamicSharedMemorySize, SMEM_BYTES);
    cudaFuncSetAttribute(k_gemm2, cudaFuncAttributeMaxDynamicSharedMemorySize, SMEM_BYTES);

    k_zero<<<1, 32>>>();
    k_count<<<T_TOK / 256, 256>>>(mask);
    k_offsets<<<1, 1>>>();
    k_scatter<<<T_TOK / 256, 256>>>(mask);

    k_cvt<<<(2 * HID * DIM / 4) / 256, 256>>>(w1, w2);

    dim3 g1(HID / BN, T_TOK / BM);
    k_gemm1<<<g1, 256, SMEM_BYTES>>>(x, b1);

    dim3 g2(DIM / BN, T_TOK / BM);
    k_gemm2<<<g2, 256, SMEM_BYTES>>>(b2, out);
}

// round 5
// speedup vs baseline: 4.1876x; 1.8415x over previous
#include <cuda_runtime.h>
#include <cuda_fp16.h>
#include <cstdint>

#define T_TOK 16384
#define DIM   1024
#define HID   4096

#define BM 128
#define BN 256
#define BK 32                      // 32 halves = 64B of K per stage row
#define S  3                       // pipeline stages

#define PADB 80                    // smem bytes per row (32 halves = 64B data + 16B pad)
#define A_ST_BYTES (BM * PADB)     // 10240
#define B_ST_BYTES (BN * PADB)     // 20480
#define STAGE_BYTES (A_ST_BYTES + B_ST_BYTES)   // 30720
#define SMEM_BYTES (S * STAGE_BYTES)            // 92160

// ---------------- scratch (static __device__ — allocation-free) ----------------
__device__ __half g_Xh[(size_t)T_TOK * DIM];    // gathered, K-masked, fp16
__device__ __half g_Hh[(size_t)T_TOK * HID];    // hidden acts, gathered order, fp16
__device__ __half g_w1h[(size_t)HID * DIM];     // w1 fp16
__device__ __half g_w2h[(size_t)DIM * HID];     // w2 fp16
__device__ int g_perm[T_TOK];
__device__ int g_rowd[T_TOK];
__device__ int g_cnt[4], g_off[4], g_cur[4];

// ---------------- PTX helpers ----------------
__device__ __forceinline__ uint32_t smem_u32(const void* p) {
    return (uint32_t)__cvta_generic_to_shared(p);
}
__device__ __forceinline__ float gelu_exact(float v) {
    return 0.5f * v * (1.0f + erff(v * 0.70710678118654752f));
}
__device__ __forceinline__ void cpa16(uint32_t saddr, const void* g) {
    asm volatile("cp.async.cg.shared.global [%0], [%1], 16;\n" :: "r"(saddr), "l"(g));
}
__device__ __forceinline__ void cp_commit() {
    asm volatile("cp.async.commit_group;\n" ::: "memory");
}
__device__ __forceinline__ void cp_wait1() {
    asm volatile("cp.async.wait_group 1;\n" ::: "memory");
}

#define LDSM_X4(r0, r1, r2, r3, addr) \
    asm volatile("ldmatrix.sync.aligned.m8n8.x4.shared.b16 {%0,%1,%2,%3}, [%4];" \
        : "=r"(r0), "=r"(r1), "=r"(r2), "=r"(r3) : "r"(addr))

__device__ __forceinline__ void mma16(float* c, const uint32_t* a, uint32_t b0, uint32_t b1) {
    asm volatile(
        "mma.sync.aligned.m16n8k16.row.col.f32.f16.f16.f32 "
        "{%0,%1,%2,%3}, {%4,%5,%6,%7}, {%8,%9}, {%0,%1,%2,%3};\n"
        : "+f"(c[0]), "+f"(c[1]), "+f"(c[2]), "+f"(c[3])
        : "r"(a[0]), "r"(a[1]), "r"(a[2]), "r"(a[3]), "r"(b0), "r"(b1));
}

// ---------------- token sort ----------------
__global__ void k_zero() {
    if (threadIdx.x < 4) { g_cnt[threadIdx.x] = 0; g_cur[threadIdx.x] = 0; }
}
__global__ void k_count(const int* __restrict__ mask) {
    int t = blockIdx.x * blockDim.x + threadIdx.x;
    if (t < T_TOK) atomicAdd(&g_cnt[mask[t]], 1);
}
__global__ void k_offsets() {
    int s = 0;
    for (int e = 0; e < 4; e++) { g_off[e] = s; s += g_cnt[e]; }
}
__global__ void k_scatter(const int* __restrict__ mask) {
    int t = blockIdx.x * blockDim.x + threadIdx.x;
    if (t < T_TOK) {
        int e = mask[t];
        int p = g_off[e] + atomicAdd(&g_cur[e], 1);
        g_perm[p] = t;
        g_rowd[p] = 128 << e;
    }
}

// ---------------- prep: gathered + K-masked + fp16 x ----------------
__global__ void k_prep(const float* __restrict__ x) {
    const int row = blockIdx.x;
    const int i   = threadIdx.x;              // 256 threads, 4 elems each
    const int tok = g_perm[row];
    const int d   = g_rowd[row];
    const int col = i * 4;
    __half2 lo = __floats2half2_rn(0.f, 0.f), hi = lo;
    if (col < d) {
        float4 v = ((const float4*)(x + (size_t)tok * DIM))[i];
        lo = __floats2half2_rn(v.x, v.y);
        hi = __floats2half2_rn(v.z, v.w);
    }
    __half2* p = (__half2*)(g_Xh + (size_t)row * DIM) + 2 * i;
    p[0] = lo; p[1] = hi;
}

// ---------------- weight conversion f32 -> fp16 ----------------
__global__ void k_cvt(const float* __restrict__ w1, const float* __restrict__ w2) {
    const int i = blockIdx.x * blockDim.x + threadIdx.x;
    const int n1 = HID * DIM / 4;
    const float4 v = (i < n1) ? ((const float4*)w1)[i] : ((const float4*)w2)[i - n1];
    __half2* p = (i < n1) ? ((__half2*)g_w1h + 2 * i) : ((__half2*)g_w2h + 2 * (i - n1));
    p[0] = __floats2half2_rn(v.x, v.y);
    p[1] = __floats2half2_rn(v.z, v.w);
}

// ---------------- stage loader: all 256 threads ----------------
__device__ __forceinline__ void stage_load(uint32_t dst, const __half* __restrict__ A,
                                           const __half* __restrict__ B,
                                           int astr, int bstr, int k0, int tid) {
#pragma unroll
    for (int i = 0; i < 2; i++) {              // A: 512 16B-chunks
        const int cid = tid + i * 256;
        const int row = cid >> 2, c = cid & 3;
        cpa16(dst + row * PADB + c * 16, A + (size_t)row * astr + k0 + c * 8);
    }
#pragma unroll
    for (int i = 0; i < 4; i++) {              // B: 1024 chunks
        const int cid = tid + i * 256;
        const int row = cid >> 2, c = cid & 3;
        cpa16(dst + A_ST_BYTES + row * PADB + c * 16, B + (size_t)row * bstr + k0 + c * 8);
    }
}

// ---------------- per-stage compute: warp tile 64x64, m16n8k16 ----------------
__device__ __forceinline__ void tile_compute(uint32_t sA, uint32_t sB,
                                             float (&acc)[4][8][4],
                                             int wm, int wn, int lane) {
    const int lr   = lane & 7;
    const int abit = (lane >> 3) & 1;
    const int cbit = (lane >> 4) & 1;
#pragma unroll
    for (int kc = 0; kc < 2; kc++) {
        uint32_t a[4][4], b[4][4];
#pragma unroll
        for (int mi = 0; mi < 4; mi++) {
            const uint32_t addr = sA + (uint32_t)((wm * 64 + mi * 16 + lr + abit * 8) * PADB
                                                  + kc * 32 + cbit * 16);
            LDSM_X4(a[mi][0], a[mi][1], a[mi][2], a[mi][3], addr);
        }
#pragma unroll
        for (int g = 0; g < 4; g++) {
            const uint32_t addr = sB + (uint32_t)((wn * 64 + g * 16 + lr + cbit * 8) * PADB
                                                  + kc * 32 + abit * 16);
            LDSM_X4(b[g][0], b[g][1], b[g][2], b[g][3], addr);
        }
#pragma unroll
        for (int mi = 0; mi < 4; mi++)
#pragma unroll
            for (int g = 0; g < 4; g++) {
                mma16(acc[mi][2 * g],     a[mi], b[g][0], b[g][1]);
                mma16(acc[mi][2 * g + 1], a[mi], b[g][2], b[g][3]);
            }
    }
}

// ---------------- GEMM mainloop (shared) ----------------
__device__ __forceinline__ void gemm_main(const __half* __restrict__ A,
                                          const __half* __restrict__ B,
                                          int astr, int bstr, int nk,
                                          uint32_t sb, float (&acc)[4][8][4],
                                          int tid, int wm, int wn, int lane) {
    stage_load(sb, A, B, astr, bstr, 0, tid);
    cp_commit();
    stage_load(sb + STAGE_BYTES, A, B, astr, bstr, BK, tid);
    cp_commit();
    for (int it = 0; it < nk; it++) {
        cp_wait1();
        __syncthreads();
        const int nx = it + 2;
        if (nx < nk) stage_load(sb + (nx % S) * STAGE_BYTES, A, B, astr, bstr, nx * BK, tid);
        cp_commit();
        const uint32_t st = sb + (it % S) * STAGE_BYTES;
        tile_compute(st, st + A_ST_BYTES, acc, wm, wn, lane);
    }
}

// ---------------- GEMM1: H = gelu(Xh @ W1h^T + b1) ----------------
__global__ void __launch_bounds__(256, 1)
k_gemm1(const float* __restrict__ b1) {
    extern __shared__ char smdyn[];
    const uint32_t sb = smem_u32(smdyn);

    const int n0   = blockIdx.x * BN;
    const int row0 = blockIdx.y * BM;
    const int tid  = threadIdx.x;
    const int lane = tid & 31, wid = tid >> 5;
    const int wm = wid >> 2, wn = wid & 3;

    float acc[4][8][4];
#pragma unroll
    for (int mi = 0; mi < 4; mi++)
#pragma unroll
        for (int ni = 0; ni < 8; ni++)
#pragma unroll
            for (int r = 0; r < 4; r++) acc[mi][ni][r] = 0.0f;

    const int nk = g_rowd[row0 + BM - 1] / BK;   // sorted rows: last = max d (>= 4)

    gemm_main(g_Xh + (size_t)row0 * DIM, g_w1h + (size_t)n0 * DIM,
              DIM, DIM, nk, sb, acc, tid, wm, wn, lane);

    // epilogue: bias + exact gelu -> fp16 into g_Hh
#pragma unroll
    for (int mi = 0; mi < 4; mi++) {
        const int r = wm * 64 + mi * 16 + (lane >> 2);
#pragma unroll
        for (int hh = 0; hh < 2; hh++) {
            __half* hp = g_Hh + (size_t)(row0 + r + hh * 8) * HID + n0;
#pragma unroll
            for (int ni = 0; ni < 8; ni++) {
                const int col = wn * 64 + ni * 8 + 2 * (lane & 3);
                const float2 bb = *(const float2*)(b1 + n0 + col);
                float v0 = gelu_exact(acc[mi][ni][hh * 2 + 0] + bb.x);
                float v1 = gelu_exact(acc[mi][ni][hh * 2 + 1] + bb.y);
                *(__half2*)(hp + col) = __floats2half2_rn(v0, v1);
            }
        }
    }
}

// ---------------- GEMM2: Y = mask_out(H @ W2h^T + b2), scattered ----------------
__global__ void __launch_bounds__(256, 1)
k_gemm2(const float* __restrict__ b2, float* __restrict__ out) {
    extern __shared__ char smdyn[];
    const uint32_t sb = smem_u32(smdyn);

    const int n0   = blockIdx.x * BN;
    const int row0 = blockIdx.y * BM;
    const int tid  = threadIdx.x;
    const int dmax = g_rowd[row0 + BM - 1];

    if (n0 >= dmax) {   // whole tile masked -> zero-fill (block-uniform)
        const int row = tid >> 1, half = tid & 1;
        const int tok = g_perm[row0 + row];
        float4* op = (float4*)(out + (size_t)tok * DIM + n0 + half * 128);
        const float4 z = make_float4(0.f, 0.f, 0.f, 0.f);
#pragma unroll
        for (int j = 0; j < 32; j++) op[j] = z;
        return;
    }

    const int lane = tid & 31, wid = tid >> 5;
    const int wm = wid >> 2, wn = wid & 3;

    float acc[4][8][4];
#pragma unroll
    for (int mi = 0; mi < 4; mi++)
#pragma unroll
        for (int ni = 0; ni < 8; ni++)
#pragma unroll
            for (int r = 0; r < 4; r++) acc[mi][ni][r] = 0.0f;

    gemm_main(g_Hh + (size_t)row0 * HID, g_w2h + (size_t)n0 * HID,
              HID, HID, HID / BK, sb, acc, tid, wm, wn, lane);

    // epilogue: bias + output mask, scatter back to token order
#pragma unroll
    for (int mi = 0; mi < 4; mi++) {
        const int r = wm * 64 + mi * 16 + (lane >> 2);
#pragma unroll
        for (int hh = 0; hh < 2; hh++) {
            const int grow = row0 + r + hh * 8;
            const int tok  = g_perm[grow];
            const int d    = g_rowd[grow];
            float* op = out + (size_t)tok * DIM;
#pragma unroll
            for (int ni = 0; ni < 8; ni++) {
                const int col = n0 + wn * 64 + ni * 8 + 2 * (lane & 3);
                float2 rr;
                if (col < d) {   // d multiple of 128, col even -> pair uniform
                    const float2 bb = *(const float2*)(b2 + col);
                    rr = make_float2(acc[mi][ni][hh * 2 + 0] + bb.x,
                                     acc[mi][ni][hh * 2 + 1] + bb.y);
                } else {
                    rr = make_float2(0.f, 0.f);
                }
                *(float2*)(op + col) = rr;
            }
        }
    }
}

// ---------------- launch ----------------
extern "C" void kernel_launch(void* const* d_in, const int* in_sizes, int n_in,
                              void* d_out, int out_size) {
    const float* x    = (const float*)d_in[0];
    const float* w1   = (const float*)d_in[1];
    const float* b1   = (const float*)d_in[2];
    const float* w2   = (const float*)d_in[3];
    const float* b2   = (const float*)d_in[4];
    const int*   mask = (const int*)d_in[5];
    float* out = (float*)d_out;

    cudaFuncSetAttribute(k_gemm1, cudaFuncAttributeMaxDynamicSharedMemorySize, SMEM_BYTES);
    cudaFuncSetAttribute(k_gemm2, cudaFuncAttributeMaxDynamicSharedMemorySize, SMEM_BYTES);

    k_zero<<<1, 32>>>();
    k_count<<<T_TOK / 256, 256>>>(mask);
    k_offsets<<<1, 1>>>();
    k_scatter<<<T_TOK / 256, 256>>>(mask);

    k_cvt<<<(2 * HID * DIM / 4) / 256, 256>>>(w1, w2);
    k_prep<<<T_TOK, 256>>>(x);

    dim3 g1(HID / BN, T_TOK / BM);
    k_gemm1<<<g1, 256, SMEM_BYTES>>>(b1);

    dim3 g2(DIM / BN, T_TOK / BM);
    k_gemm2<<<g2, 256, SMEM_BYTES>>>(b2, out);
}

// round 6
// speedup vs baseline: 4.7512x; 1.1346x over previous
#include <cuda_runtime.h>
#include <cuda_fp16.h>
#include <cstdint>

#define T_TOK 16384
#define DIM   1024
#define HID   4096

#define BM 128
#define BN 256
#define BK 64                      // 64 halves = 128B of K per stage row
#define S  3                       // pipeline stages

#define PADB 144                   // smem bytes per row (128B data + 16B pad)
#define A_ST_BYTES (BM * PADB)     // 18432
#define B_ST_BYTES (BN * PADB)     // 36864
#define STAGE_BYTES (A_ST_BYTES + B_ST_BYTES)   // 55296
#define SMEM_BYTES (S * STAGE_BYTES)            // 165888

// ---------------- scratch (static __device__ — allocation-free) ----------------
__device__ __half g_Xh[(size_t)T_TOK * DIM];    // gathered, K-masked, fp16
__device__ __half g_Hh[(size_t)T_TOK * HID];    // hidden acts, gathered order, fp16
__device__ __half g_w1h[(size_t)HID * DIM];     // w1 fp16
__device__ __half g_w2h[(size_t)DIM * HID];     // w2 fp16
__device__ int g_perm[T_TOK];
__device__ int g_rowd[T_TOK];
__device__ int g_off[4], g_cur[4];

// ---------------- PTX helpers ----------------
__device__ __forceinline__ uint32_t smem_u32(const void* p) {
    return (uint32_t)__cvta_generic_to_shared(p);
}
__device__ __forceinline__ float gelu_exact(float v) {
    return 0.5f * v * (1.0f + erff(v * 0.70710678118654752f));
}
__device__ __forceinline__ void cpa16(uint32_t saddr, const void* g) {
    asm volatile("cp.async.cg.shared.global [%0], [%1], 16;\n" :: "r"(saddr), "l"(g));
}
__device__ __forceinline__ void cp_commit() {
    asm volatile("cp.async.commit_group;\n" ::: "memory");
}
__device__ __forceinline__ void cp_wait1() {
    asm volatile("cp.async.wait_group 1;\n" ::: "memory");
}

#define LDSM_X4(r0, r1, r2, r3, addr) \
    asm volatile("ldmatrix.sync.aligned.m8n8.x4.shared.b16 {%0,%1,%2,%3}, [%4];" \
        : "=r"(r0), "=r"(r1), "=r"(r2), "=r"(r3) : "r"(addr))

__device__ __forceinline__ void mma16(float* c, const uint32_t* a, uint32_t b0, uint32_t b1) {
    asm volatile(
        "mma.sync.aligned.m16n8k16.row.col.f32.f16.f16.f32 "
        "{%0,%1,%2,%3}, {%4,%5,%6,%7}, {%8,%9}, {%0,%1,%2,%3};\n"
        : "+f"(c[0]), "+f"(c[1]), "+f"(c[2]), "+f"(c[3])
        : "r"(a[0]), "r"(a[1]), "r"(a[2]), "r"(a[3]), "r"(b0), "r"(b1));
}

// ---------------- launch 0: histogram + offsets (one CTA) ----------------
__global__ void k_hist(const int* __restrict__ mask) {
    const int tid = threadIdx.x;          // 1024 threads
    int c0 = 0, c1 = 0, c2 = 0, c3 = 0;
    for (int i = tid; i < T_TOK; i += 1024) {
        const int e = mask[i];
        c0 += (e == 0); c1 += (e == 1); c2 += (e == 2); c3 += (e == 3);
    }
#pragma unroll
    for (int o = 16; o; o >>= 1) {
        c0 += __shfl_xor_sync(~0u, c0, o);
        c1 += __shfl_xor_sync(~0u, c1, o);
        c2 += __shfl_xor_sync(~0u, c2, o);
        c3 += __shfl_xor_sync(~0u, c3, o);
    }
    __shared__ int sh[4];
    if (tid < 4) sh[tid] = 0;
    __syncthreads();
    if ((tid & 31) == 0) {
        atomicAdd(&sh[0], c0); atomicAdd(&sh[1], c1);
        atomicAdd(&sh[2], c2); atomicAdd(&sh[3], c3);
    }
    __syncthreads();
    if (tid == 0) {
        int s = 0;
        for (int e = 0; e < 4; e++) { g_off[e] = s; s += sh[e]; g_cur[e] = 0; }
    }
}

// ---------------- launch 1: scatter rank + gather + K-mask + fp16 convert ----------------
__global__ void k_scatter_prep(const float* __restrict__ x, const int* __restrict__ mask) {
    const int t = blockIdx.x;             // one block per token, 128 threads
    __shared__ int sp, sd;
    if (threadIdx.x == 0) {
        const int e = mask[t];
        const int p = g_off[e] + atomicAdd(&g_cur[e], 1);
        const int d = 128 << e;
        g_perm[p] = t;
        g_rowd[p] = d;
        sp = p; sd = d;
    }
    __syncthreads();
    const int p = sp, d = sd;
    const int i = threadIdx.x;            // 8 floats per thread
    const float4* xp = (const float4*)(x + (size_t)t * DIM);
    uint4 r = make_uint4(0u, 0u, 0u, 0u);
    if (i * 8 < d) {                      // d multiple of 128 -> chunk fully in/out
        const float4 v0 = xp[2 * i];
        const float4 v1 = xp[2 * i + 1];
        __half2 h0 = __floats2half2_rn(v0.x, v0.y);
        __half2 h1 = __floats2half2_rn(v0.z, v0.w);
        __half2 h2 = __floats2half2_rn(v1.x, v1.y);
        __half2 h3 = __floats2half2_rn(v1.z, v1.w);
        r.x = *(uint32_t*)&h0; r.y = *(uint32_t*)&h1;
        r.z = *(uint32_t*)&h2; r.w = *(uint32_t*)&h3;
    }
    ((uint4*)(g_Xh + (size_t)p * DIM))[i] = r;
}

// ---------------- launch 2: weight conversion f32 -> fp16 ----------------
__global__ void k_cvt(const float* __restrict__ w1, const float* __restrict__ w2) {
    const int i = blockIdx.x * blockDim.x + threadIdx.x;
    const int n1 = HID * DIM / 4;
    const float4 v = (i < n1) ? ((const float4*)w1)[i] : ((const float4*)w2)[i - n1];
    __half2* p = (i < n1) ? ((__half2*)g_w1h + 2 * i) : ((__half2*)g_w2h + 2 * (i - n1));
    p[0] = __floats2half2_rn(v.x, v.y);
    p[1] = __floats2half2_rn(v.z, v.w);
}

// ---------------- stage loader: all 256 threads, 48KB per stage ----------------
__device__ __forceinline__ void stage_load(uint32_t dst, const __half* __restrict__ A,
                                           const __half* __restrict__ B,
                                           int astr, int bstr, int k0, int tid) {
#pragma unroll
    for (int i = 0; i < 4; i++) {              // A: 1024 16B-chunks (128 rows x 8)
        const int cid = tid + i * 256;
        const int row = cid >> 3, c = cid & 7;
        cpa16(dst + row * PADB + c * 16, A + (size_t)row * astr + k0 + c * 8);
    }
#pragma unroll
    for (int i = 0; i < 8; i++) {              // B: 2048 chunks (256 rows x 8)
        const int cid = tid + i * 256;
        const int row = cid >> 3, c = cid & 7;
        cpa16(dst + A_ST_BYTES + row * PADB + c * 16, B + (size_t)row * bstr + k0 + c * 8);
    }
}

// ---------------- per-stage compute: warp tile 64x64, m16n8k16, 4 K-chunks ----------------
__device__ __forceinline__ void tile_compute(uint32_t sA, uint32_t sB,
                                             float (&acc)[4][8][4],
                                             int wm, int wn, int lane) {
    const int lr   = lane & 7;
    const int abit = (lane >> 3) & 1;
    const int cbit = (lane >> 4) & 1;
#pragma unroll
    for (int kc = 0; kc < 4; kc++) {
        uint32_t a[4][4], b[4][4];
#pragma unroll
        for (int mi = 0; mi < 4; mi++) {
            const uint32_t addr = sA + (uint32_t)((wm * 64 + mi * 16 + lr + abit * 8) * PADB
                                                  + kc * 32 + cbit * 16);
            LDSM_X4(a[mi][0], a[mi][1], a[mi][2], a[mi][3], addr);
        }
#pragma unroll
        for (int g = 0; g < 4; g++) {
            const uint32_t addr = sB + (uint32_t)((wn * 64 + g * 16 + lr + cbit * 8) * PADB
                                                  + kc * 32 + abit * 16);
            LDSM_X4(b[g][0], b[g][1], b[g][2], b[g][3], addr);
        }
#pragma unroll
        for (int mi = 0; mi < 4; mi++)
#pragma unroll
            for (int g = 0; g < 4; g++) {
                mma16(acc[mi][2 * g],     a[mi], b[g][0], b[g][1]);
                mma16(acc[mi][2 * g + 1], a[mi], b[g][2], b[g][3]);
            }
    }
}

// ---------------- GEMM mainloop (shared) ----------------
__device__ __forceinline__ void gemm_main(const __half* __restrict__ A,
                                          const __half* __restrict__ B,
                                          int astr, int bstr, int nk,
                                          uint32_t sb, float (&acc)[4][8][4],
                                          int tid, int wm, int wn, int lane) {
    stage_load(sb, A, B, astr, bstr, 0, tid);
    cp_commit();
    stage_load(sb + STAGE_BYTES, A, B, astr, bstr, BK, tid);
    cp_commit();
    for (int it = 0; it < nk; it++) {
        cp_wait1();
        __syncthreads();
        const int nx = it + 2;
        if (nx < nk) stage_load(sb + (nx % S) * STAGE_BYTES, A, B, astr, bstr, nx * BK, tid);
        cp_commit();
        const uint32_t st = sb + (it % S) * STAGE_BYTES;
        tile_compute(st, st + A_ST_BYTES, acc, wm, wn, lane);
    }
}

// ---------------- launch 3 — GEMM1: H = gelu(Xh @ W1h^T + b1) ----------------
__global__ void __launch_bounds__(256, 1)
k_gemm1(const float* __restrict__ b1) {
    extern __shared__ char smdyn[];
    const uint32_t sb = smem_u32(smdyn);

    const int n0   = blockIdx.x * BN;
    const int row0 = blockIdx.y * BM;
    const int tid  = threadIdx.x;
    const int lane = tid & 31, wid = tid >> 5;
    const int wm = wid >> 2, wn = wid & 3;

    float acc[4][8][4];
#pragma unroll
    for (int mi = 0; mi < 4; mi++)
#pragma unroll
        for (int ni = 0; ni < 8; ni++)
#pragma unroll
            for (int r = 0; r < 4; r++) acc[mi][ni][r] = 0.0f;

    const int nk = g_rowd[row0 + BM - 1] / BK;   // sorted rows: last = max d; >= 2

    gemm_main(g_Xh + (size_t)row0 * DIM, g_w1h + (size_t)n0 * DIM,
              DIM, DIM, nk, sb, acc, tid, wm, wn, lane);

    // epilogue: bias + exact gelu -> fp16 into g_Hh
#pragma unroll
    for (int mi = 0; mi < 4; mi++) {
        const int r = wm * 64 + mi * 16 + (lane >> 2);
#pragma unroll
        for (int hh = 0; hh < 2; hh++) {
            __half* hp = g_Hh + (size_t)(row0 + r + hh * 8) * HID + n0;
#pragma unroll
            for (int ni = 0; ni < 8; ni++) {
                const int col = wn * 64 + ni * 8 + 2 * (lane & 3);
                const float2 bb = *(const float2*)(b1 + n0 + col);
                float v0 = gelu_exact(acc[mi][ni][hh * 2 + 0] + bb.x);
                float v1 = gelu_exact(acc[mi][ni][hh * 2 + 1] + bb.y);
                *(__half2*)(hp + col) = __floats2half2_rn(v0, v1);
            }
        }
    }
}

// ---------------- launch 4 — GEMM2: Y = mask_out(H @ W2h^T + b2), scattered ----------------
__global__ void __launch_bounds__(256, 1)
k_gemm2(const float* __restrict__ b2, float* __restrict__ out) {
    extern __shared__ char smdyn[];
    const uint32_t sb = smem_u32(smdyn);

    const int n0   = blockIdx.x * BN;
    const int row0 = blockIdx.y * BM;
    const int tid  = threadIdx.x;
    const int dmax = g_rowd[row0 + BM - 1];

    if (n0 >= dmax) {   // whole tile masked -> zero-fill (block-uniform)
        const int row = tid >> 1, half = tid & 1;
        const int tok = g_perm[row0 + row];
        float4* op = (float4*)(out + (size_t)tok * DIM + n0 + half * 128);
        const float4 z = make_float4(0.f, 0.f, 0.f, 0.f);
#pragma unroll
        for (int j = 0; j < 32; j++) op[j] = z;
        return;
    }

    const int lane = tid & 31, wid = tid >> 5;
    const int wm = wid >> 2, wn = wid & 3;

    float acc[4][8][4];
#pragma unroll
    for (int mi = 0; mi < 4; mi++)
#pragma unroll
        for (int ni = 0; ni < 8; ni++)
#pragma unroll
            for (int r = 0; r < 4; r++) acc[mi][ni][r] = 0.0f;

    gemm_main(g_Hh + (size_t)row0 * HID, g_w2h + (size_t)n0 * HID,
              HID, HID, HID / BK, sb, acc, tid, wm, wn, lane);

    // epilogue: bias + output mask, scatter back to token order
#pragma unroll
    for (int mi = 0; mi < 4; mi++) {
        const int r = wm * 64 + mi * 16 + (lane >> 2);
#pragma unroll
        for (int hh = 0; hh < 2; hh++) {
            const int grow = row0 + r + hh * 8;
            const int tok  = g_perm[grow];
            const int d    = g_rowd[grow];
            float* op = out + (size_t)tok * DIM;
#pragma unroll
            for (int ni = 0; ni < 8; ni++) {
                const int col = n0 + wn * 64 + ni * 8 + 2 * (lane & 3);
                float2 rr;
                if (col < d) {   // d multiple of 128, col even -> pair uniform
                    const float2 bb = *(const float2*)(b2 + col);
                    rr = make_float2(acc[mi][ni][hh * 2 + 0] + bb.x,
                                     acc[mi][ni][hh * 2 + 1] + bb.y);
                } else {
                    rr = make_float2(0.f, 0.f);
                }
                *(float2*)(op + col) = rr;
            }
        }
    }
}

// ---------------- launch ----------------
extern "C" void kernel_launch(void* const* d_in, const int* in_sizes, int n_in,
                              void* d_out, int out_size) {
    const float* x    = (const float*)d_in[0];
    const float* w1   = (const float*)d_in[1];
    const float* b1   = (const float*)d_in[2];
    const float* w2   = (const float*)d_in[3];
    const float* b2   = (const float*)d_in[4];
    const int*   mask = (const int*)d_in[5];
    float* out = (float*)d_out;

    cudaFuncSetAttribute(k_gemm1, cudaFuncAttributeMaxDynamicSharedMemorySize, SMEM_BYTES);
    cudaFuncSetAttribute(k_gemm2, cudaFuncAttributeMaxDynamicSharedMemorySize, SMEM_BYTES);

    k_hist<<<1, 1024>>>(mask);                       // launch 0
    k_scatter_prep<<<T_TOK, 128>>>(x, mask);         // launch 1
    k_cvt<<<(2 * HID * DIM / 4) / 256, 256>>>(w1, w2);  // launch 2

    dim3 g1(HID / BN, T_TOK / BM);
    k_gemm1<<<g1, 256, SMEM_BYTES>>>(b1);            // launch 3

    dim3 g2(DIM / BN, T_TOK / BM);
    k_gemm2<<<g2, 256, SMEM_BYTES>>>(b2, out);       // launch 4
}

// round 7
// speedup vs baseline: 4.9014x; 1.0316x over previous
#include <cuda_runtime.h>
#include <cuda_fp16.h>
#include <cstdint>

#define T_TOK 16384
#define DIM   1024
#define HID   4096

#define BM 128
#define BN 256
#define BK 64                      // 64 halves = 128B of K per stage row
#define S  3                       // pipeline stages
#define NT 512                     // 16 warps: 4x4 grid, warp tile 32x64

#define PADB 144                   // smem bytes per row (128B data + 16B pad)
#define A_ST_BYTES (BM * PADB)     // 18432
#define B_ST_BYTES (BN * PADB)     // 36864
#define STAGE_BYTES (A_ST_BYTES + B_ST_BYTES)   // 55296
#define SMEM_BYTES (S * STAGE_BYTES)            // 165888

// ---------------- scratch (static __device__ — allocation-free) ----------------
__device__ __half g_Xh[(size_t)T_TOK * DIM];    // gathered, K-masked, fp16
__device__ __half g_Hh[(size_t)T_TOK * HID];    // hidden acts, gathered order, fp16
__device__ __half g_w1h[(size_t)HID * DIM];     // w1 fp16
__device__ __half g_w2h[(size_t)DIM * HID];     // w2 fp16
__device__ int g_perm[T_TOK];
__device__ int g_rowd[T_TOK];
__device__ int g_off[4], g_cur[4];

// ---------------- PTX helpers ----------------
__device__ __forceinline__ uint32_t smem_u32(const void* p) {
    return (uint32_t)__cvta_generic_to_shared(p);
}
__device__ __forceinline__ float gelu_exact(float v) {
    return 0.5f * v * (1.0f + erff(v * 0.70710678118654752f));
}
__device__ __forceinline__ void cpa16(uint32_t saddr, const void* g) {
    asm volatile("cp.async.cg.shared.global [%0], [%1], 16;\n" :: "r"(saddr), "l"(g));
}
__device__ __forceinline__ void cp_commit() {
    asm volatile("cp.async.commit_group;\n" ::: "memory");
}
__device__ __forceinline__ void cp_wait1() {
    asm volatile("cp.async.wait_group 1;\n" ::: "memory");
}

#define LDSM_X4(r0, r1, r2, r3, addr) \
    asm volatile("ldmatrix.sync.aligned.m8n8.x4.shared.b16 {%0,%1,%2,%3}, [%4];" \
        : "=r"(r0), "=r"(r1), "=r"(r2), "=r"(r3) : "r"(addr))

__device__ __forceinline__ void mma16(float* c, const uint32_t* a, uint32_t b0, uint32_t b1) {
    asm volatile(
        "mma.sync.aligned.m16n8k16.row.col.f32.f16.f16.f32 "
        "{%0,%1,%2,%3}, {%4,%5,%6,%7}, {%8,%9}, {%0,%1,%2,%3};\n"
        : "+f"(c[0]), "+f"(c[1]), "+f"(c[2]), "+f"(c[3])
        : "r"(a[0]), "r"(a[1]), "r"(a[2]), "r"(a[3]), "r"(b0), "r"(b1));
}

// ---------------- launch 0: histogram + offsets (one CTA) ----------------
__global__ void k_hist(const int* __restrict__ mask) {
    const int tid = threadIdx.x;          // 1024 threads
    int c0 = 0, c1 = 0, c2 = 0, c3 = 0;
    for (int i = tid; i < T_TOK; i += 1024) {
        const int e = mask[i];
        c0 += (e == 0); c1 += (e == 1); c2 += (e == 2); c3 += (e == 3);
    }
#pragma unroll
    for (int o = 16; o; o >>= 1) {
        c0 += __shfl_xor_sync(~0u, c0, o);
        c1 += __shfl_xor_sync(~0u, c1, o);
        c2 += __shfl_xor_sync(~0u, c2, o);
        c3 += __shfl_xor_sync(~0u, c3, o);
    }
    __shared__ int sh[4];
    if (tid < 4) sh[tid] = 0;
    __syncthreads();
    if ((tid & 31) == 0) {
        atomicAdd(&sh[0], c0); atomicAdd(&sh[1], c1);
        atomicAdd(&sh[2], c2); atomicAdd(&sh[3], c3);
    }
    __syncthreads();
    if (tid == 0) {
        int s = 0;
        for (int e = 0; e < 4; e++) { g_off[e] = s; s += sh[e]; g_cur[e] = 0; }
    }
}

// ---------------- launch 1: scatter rank + gather + K-mask + fp16 convert ----------------
__global__ void k_scatter_prep(const float* __restrict__ x, const int* __restrict__ mask) {
    const int t = blockIdx.x;             // one block per token, 128 threads
    __shared__ int sp, sd;
    if (threadIdx.x == 0) {
        const int e = mask[t];
        const int p = g_off[e] + atomicAdd(&g_cur[e], 1);
        const int d = 128 << e;
        g_perm[p] = t;
        g_rowd[p] = d;
        sp = p; sd = d;
    }
    __syncthreads();
    const int p = sp, d = sd;
    const int i = threadIdx.x;            // 8 floats per thread
    const float4* xp = (const float4*)(x + (size_t)t * DIM);
    uint4 r = make_uint4(0u, 0u, 0u, 0u);
    if (i * 8 < d) {                      // d multiple of 128 -> chunk fully in/out
        const float4 v0 = xp[2 * i];
        const float4 v1 = xp[2 * i + 1];
        __half2 h0 = __floats2half2_rn(v0.x, v0.y);
        __half2 h1 = __floats2half2_rn(v0.z, v0.w);
        __half2 h2 = __floats2half2_rn(v1.x, v1.y);
        __half2 h3 = __floats2half2_rn(v1.z, v1.w);
        r.x = *(uint32_t*)&h0; r.y = *(uint32_t*)&h1;
        r.z = *(uint32_t*)&h2; r.w = *(uint32_t*)&h3;
    }
    ((uint4*)(g_Xh + (size_t)p * DIM))[i] = r;
}

// ---------------- launch 2: weight conversion f32 -> fp16 ----------------
__global__ void k_cvt(const float* __restrict__ w1, const float* __restrict__ w2) {
    const int i = blockIdx.x * blockDim.x + threadIdx.x;
    const int n1 = HID * DIM / 4;
    const float4 v = (i < n1) ? ((const float4*)w1)[i] : ((const float4*)w2)[i - n1];
    __half2* p = (i < n1) ? ((__half2*)g_w1h + 2 * i) : ((__half2*)g_w2h + 2 * (i - n1));
    p[0] = __floats2half2_rn(v.x, v.y);
    p[1] = __floats2half2_rn(v.z, v.w);
}

// ---------------- stage loader: all 512 threads, 48KB per stage ----------------
__device__ __forceinline__ void stage_load(uint32_t dst, const __half* __restrict__ A,
                                           const __half* __restrict__ B,
                                           int astr, int bstr, int k0, int tid) {
#pragma unroll
    for (int i = 0; i < 2; i++) {              // A: 1024 16B-chunks (128 rows x 8)
        const int cid = tid + i * NT;
        const int row = cid >> 3, c = cid & 7;
        cpa16(dst + row * PADB + c * 16, A + (size_t)row * astr + k0 + c * 8);
    }
#pragma unroll
    for (int i = 0; i < 4; i++) {              // B: 2048 chunks (256 rows x 8)
        const int cid = tid + i * NT;
        const int row = cid >> 3, c = cid & 7;
        cpa16(dst + A_ST_BYTES + row * PADB + c * 16, B + (size_t)row * bstr + k0 + c * 8);
    }
}

// ---------------- per-stage compute: warp tile 32x64, m16n8k16, 4 K-chunks ----------------
__device__ __forceinline__ void tile_compute(uint32_t sA, uint32_t sB,
                                             float (&acc)[2][8][4],
                                             int wm, int wn, int lane) {
    const int lr   = lane & 7;
    const int abit = (lane >> 3) & 1;
    const int cbit = (lane >> 4) & 1;
#pragma unroll
    for (int kc = 0; kc < 4; kc++) {
        uint32_t a[2][4], b[4][4];
#pragma unroll
        for (int mi = 0; mi < 2; mi++) {
            const uint32_t addr = sA + (uint32_t)((wm * 32 + mi * 16 + lr + abit * 8) * PADB
                                                  + kc * 32 + cbit * 16);
            LDSM_X4(a[mi][0], a[mi][1], a[mi][2], a[mi][3], addr);
        }
#pragma unroll
        for (int g = 0; g < 4; g++) {
            const uint32_t addr = sB + (uint32_t)((wn * 64 + g * 16 + lr + cbit * 8) * PADB
                                                  + kc * 32 + abit * 16);
            LDSM_X4(b[g][0], b[g][1], b[g][2], b[g][3], addr);
        }
#pragma unroll
        for (int mi = 0; mi < 2; mi++)
#pragma unroll
            for (int g = 0; g < 4; g++) {
                mma16(acc[mi][2 * g],     a[mi], b[g][0], b[g][1]);
                mma16(acc[mi][2 * g + 1], a[mi], b[g][2], b[g][3]);
            }
    }
}

// ---------------- GEMM mainloop (shared) ----------------
__device__ __forceinline__ void gemm_main(const __half* __restrict__ A,
                                          const __half* __restrict__ B,
                                          int astr, int bstr, int nk,
                                          uint32_t sb, float (&acc)[2][8][4],
                                          int tid, int wm, int wn, int lane) {
    stage_load(sb, A, B, astr, bstr, 0, tid);
    cp_commit();
    stage_load(sb + STAGE_BYTES, A, B, astr, bstr, BK, tid);
    cp_commit();
    for (int it = 0; it < nk; it++) {
        cp_wait1();
        __syncthreads();
        const int nx = it + 2;
        if (nx < nk) stage_load(sb + (nx % S) * STAGE_BYTES, A, B, astr, bstr, nx * BK, tid);
        cp_commit();
        const uint32_t st = sb + (it % S) * STAGE_BYTES;
        tile_compute(st, st + A_ST_BYTES, acc, wm, wn, lane);
    }
}

// ---------------- launch 3 — GEMM1: H = gelu(Xh @ W1h^T + b1) ----------------
__global__ void __launch_bounds__(NT, 1)
k_gemm1(const float* __restrict__ b1) {
    extern __shared__ char smdyn[];
    const uint32_t sb = smem_u32(smdyn);

    const int n0   = blockIdx.x * BN;
    const int row0 = blockIdx.y * BM;
    const int tid  = threadIdx.x;
    const int lane = tid & 31, wid = tid >> 5;
    const int wm = wid >> 2, wn = wid & 3;

    float acc[2][8][4];
#pragma unroll
    for (int mi = 0; mi < 2; mi++)
#pragma unroll
        for (int ni = 0; ni < 8; ni++)
#pragma unroll
            for (int r = 0; r < 4; r++) acc[mi][ni][r] = 0.0f;

    const int nk = g_rowd[row0 + BM - 1] / BK;   // sorted rows: last = max d; >= 2

    gemm_main(g_Xh + (size_t)row0 * DIM, g_w1h + (size_t)n0 * DIM,
              DIM, DIM, nk, sb, acc, tid, wm, wn, lane);

    // epilogue: bias + exact gelu -> fp16 into g_Hh
#pragma unroll
    for (int mi = 0; mi < 2; mi++) {
        const int r = wm * 32 + mi * 16 + (lane >> 2);
#pragma unroll
        for (int hh = 0; hh < 2; hh++) {
            __half* hp = g_Hh + (size_t)(row0 + r + hh * 8) * HID + n0;
#pragma unroll
            for (int ni = 0; ni < 8; ni++) {
                const int col = wn * 64 + ni * 8 + 2 * (lane & 3);
                const float2 bb = *(const float2*)(b1 + n0 + col);
                float v0 = gelu_exact(acc[mi][ni][hh * 2 + 0] + bb.x);
                float v1 = gelu_exact(acc[mi][ni][hh * 2 + 1] + bb.y);
                *(__half2*)(hp + col) = __floats2half2_rn(v0, v1);
            }
        }
    }
}

// ---------------- launch 4 — GEMM2: Y = mask_out(H @ W2h^T + b2), scattered ----------------
__global__ void __launch_bounds__(NT, 1)
k_gemm2(const float* __restrict__ b2, float* __restrict__ out) {
    extern __shared__ char smdyn[];
    const uint32_t sb = smem_u32(smdyn);

    const int n0   = blockIdx.x * BN;
    const int row0 = blockIdx.y * BM;
    const int tid  = threadIdx.x;
    const int dmax = g_rowd[row0 + BM - 1];

    if (n0 >= dmax) {   // whole tile masked -> zero-fill (block-uniform)
        if (tid < 256) {
            const int row = tid >> 1, half = tid & 1;
            const int tok = g_perm[row0 + row];
            float4* op = (float4*)(out + (size_t)tok * DIM + n0 + half * 128);
            const float4 z = make_float4(0.f, 0.f, 0.f, 0.f);
#pragma unroll
            for (int j = 0; j < 32; j++) op[j] = z;
        }
        return;
    }

    const int lane = tid & 31, wid = tid >> 5;
    const int wm = wid >> 2, wn = wid & 3;

    float acc[2][8][4];
#pragma unroll
    for (int mi = 0; mi < 2; mi++)
#pragma unroll
        for (int ni = 0; ni < 8; ni++)
#pragma unroll
            for (int r = 0; r < 4; r++) acc[mi][ni][r] = 0.0f;

    gemm_main(g_Hh + (size_t)row0 * HID, g_w2h + (size_t)n0 * HID,
              HID, HID, HID / BK, sb, acc, tid, wm, wn, lane);

    // epilogue: bias + output mask, scatter back to token order
#pragma unroll
    for (int mi = 0; mi < 2; mi++) {
        const int r = wm * 32 + mi * 16 + (lane >> 2);
#pragma unroll
        for (int hh = 0; hh < 2; hh++) {
            const int grow = row0 + r + hh * 8;
            const int tok  = g_perm[grow];
            const int d    = g_rowd[grow];
            float* op = out + (size_t)tok * DIM;
#pragma unroll
            for (int ni = 0; ni < 8; ni++) {
                const int col = n0 + wn * 64 + ni * 8 + 2 * (lane & 3);
                float2 rr;
                if (col < d) {   // d multiple of 128, col even -> pair uniform
                    const float2 bb = *(const float2*)(b2 + col);
                    rr = make_float2(acc[mi][ni][hh * 2 + 0] + bb.x,
                                     acc[mi][ni][hh * 2 + 1] + bb.y);
                } else {
                    rr = make_float2(0.f, 0.f);
                }
                *(float2*)(op + col) = rr;
            }
        }
    }
}

// ---------------- launch ----------------
extern "C" void kernel_launch(void* const* d_in, const int* in_sizes, int n_in,
                              void* d_out, int out_size) {
    const float* x    = (const float*)d_in[0];
    const float* w1   = (const float*)d_in[1];
    const float* b1   = (const float*)d_in[2];
    const float* w2   = (const float*)d_in[3];
    const float* b2   = (const float*)d_in[4];
    const int*   mask = (const int*)d_in[5];
    float* out = (float*)d_out;

    cudaFuncSetAttribute(k_gemm1, cudaFuncAttributeMaxDynamicSharedMemorySize, SMEM_BYTES);
    cudaFuncSetAttribute(k_gemm2, cudaFuncAttributeMaxDynamicSharedMemorySize, SMEM_BYTES);

    k_hist<<<1, 1024>>>(mask);                       // launch 0
    k_scatter_prep<<<T_TOK, 128>>>(x, mask);         // launch 1
    k_cvt<<<(2 * HID * DIM / 4) / 256, 256>>>(w1, w2);  // launch 2

    dim3 g1(HID / BN, T_TOK / BM);
    k_gemm1<<<g1, NT, SMEM_BYTES>>>(b1);             // launch 3

    dim3 g2(DIM / BN, T_TOK / BM);
    k_gemm2<<<g2, NT, SMEM_BYTES>>>(b2, out);        // launch 4
}